// round 1
// baseline (speedup 1.0000x reference)
#include <cuda_runtime.h>

// Problem constants
#define NNODES 8192
#define DIM    512
#define NLAYER 2
#define SLOPE  0.01f

// Scratch (device globals: allocation-free per harness rules)
__device__ float g_proj[NNODES * 2 * DIM];              // 32 MB
__device__ float g_scores[(long long)NNODES * NNODES];  // 256 MB
__device__ float g_xbuf[NNODES * DIM];                  // 16 MB

// Packed fp32x2 FMA (FFMA2) — only reachable via PTX on sm_103a
#define FMA2(d, a, b) asm("fma.rn.f32x2 %0, %1, %2, %0;" : "+l"(d) : "l"(a), "l"(b))
#define PACK_DUP(d, x) do { unsigned _r = __float_as_uint(x); \
    asm("mov.b64 %0, {%1, %1};" : "=l"(d) : "r"(_r)); } while (0)
#define PACK2(d, x, y) do { unsigned _a = __float_as_uint(x), _b = __float_as_uint(y); \
    asm("mov.b64 %0, {%1, %2};" : "=l"(d) : "r"(_a), "r"(_b)); } while (0)
#define UNPK2(u, lo, hi) asm("mov.b64 {%0, %1}, %2;" : "=f"(lo), "=f"(hi) : "l"(u))

// ---------------------------------------------------------------------------
// 128x128x16 SIMT fp32 GEMM, 256 threads, 8x8 per thread, f32x2 accumulators.
// TRANS_B: B is [N,K] row-major (computes A @ B^T). EPI: out = leaky(acc + resid).
// All dims assumed multiples of tile sizes (true for this problem).
// ---------------------------------------------------------------------------
template <bool TRANS_B, bool EPI>
__global__ __launch_bounds__(256, 2)
void sgemm128(const float* __restrict__ A, int lda,
              const float* __restrict__ B, int ldb,
              float* __restrict__ C, int ldc,
              const float* __restrict__ resid, int ldr,
              int K)
{
    __shared__ float As[16][132];
    __shared__ float Bs[16][132];

    const int tid = threadIdx.x;
    const int bm = blockIdx.y * 128;
    const int bn = blockIdx.x * 128;
    const int tx = tid & 15;
    const int ty = tid >> 4;
    const int tx4 = tx * 4;
    const int ty4 = ty * 4;

    // A tile load mapping: 128 rows x 16 cols, 2 float4/thread
    const int ar = tid >> 2;          // 0..63
    const int ac = (tid & 3) * 4;     // 0,4,8,12
    const float* Aptr = A + (size_t)(bm + ar) * lda + ac;

    // B tile load mapping
    int br, bc;
    const float* Bptr;
    if (TRANS_B) {                     // B rows are N, cols are K
        br = tid >> 2;                 // n-index 0..63
        bc = (tid & 3) * 4;            // k-index
        Bptr = B + (size_t)(bn + br) * ldb + bc;
    } else {                           // B rows are K, cols are N
        br = tid >> 5;                 // k-index 0..7
        bc = (tid & 31) * 4;           // n-index
        Bptr = B + (size_t)br * ldb + bn + bc;
    }

    unsigned long long acc[8][4] = {};  // 8 rows x 4 f32x2 col-pairs

    // Prefetch tile 0 into registers
    float4 pa0 = *(const float4*)(Aptr);
    float4 pa1 = *(const float4*)(Aptr + (size_t)64 * lda);
    float4 pb0, pb1;
    if (TRANS_B) {
        pb0 = *(const float4*)(Bptr);
        pb1 = *(const float4*)(Bptr + (size_t)64 * ldb);
    } else {
        pb0 = *(const float4*)(Bptr);
        pb1 = *(const float4*)(Bptr + (size_t)8 * ldb);
    }

    const int ktiles = K >> 4;
    for (int t = 0; t < ktiles; ++t) {
        // Store prefetched tile to smem (A transposed; B transposed if TRANS_B)
        As[ac + 0][ar] = pa0.x; As[ac + 1][ar] = pa0.y;
        As[ac + 2][ar] = pa0.z; As[ac + 3][ar] = pa0.w;
        As[ac + 0][ar + 64] = pa1.x; As[ac + 1][ar + 64] = pa1.y;
        As[ac + 2][ar + 64] = pa1.z; As[ac + 3][ar + 64] = pa1.w;
        if (TRANS_B) {
            Bs[bc + 0][br] = pb0.x; Bs[bc + 1][br] = pb0.y;
            Bs[bc + 2][br] = pb0.z; Bs[bc + 3][br] = pb0.w;
            Bs[bc + 0][br + 64] = pb1.x; Bs[bc + 1][br + 64] = pb1.y;
            Bs[bc + 2][br + 64] = pb1.z; Bs[bc + 3][br + 64] = pb1.w;
        } else {
            *(float4*)&Bs[br][bc]     = pb0;
            *(float4*)&Bs[br + 8][bc] = pb1;
        }
        __syncthreads();

        // Prefetch next tile (LDG latency overlapped with compute below)
        if (t + 1 < ktiles) {
            Aptr += 16;
            pa0 = *(const float4*)(Aptr);
            pa1 = *(const float4*)(Aptr + (size_t)64 * lda);
            if (TRANS_B) {
                Bptr += 16;
                pb0 = *(const float4*)(Bptr);
                pb1 = *(const float4*)(Bptr + (size_t)64 * ldb);
            } else {
                Bptr += (size_t)16 * ldb;
                pb0 = *(const float4*)(Bptr);
                pb1 = *(const float4*)(Bptr + (size_t)8 * ldb);
            }
        }

        // Compute 16 k-steps with packed f32x2 FMAs
        #pragma unroll
        for (int kk = 0; kk < 16; ++kk) {
            float4 a0 = *(const float4*)&As[kk][ty4];
            float4 a1 = *(const float4*)&As[kk][64 + ty4];
            float4 b0 = *(const float4*)&Bs[kk][tx4];
            float4 b1 = *(const float4*)&Bs[kk][64 + tx4];
            unsigned long long bp0, bp1, bp2, bp3;
            PACK2(bp0, b0.x, b0.y); PACK2(bp1, b0.z, b0.w);
            PACK2(bp2, b1.x, b1.y); PACK2(bp3, b1.z, b1.w);
            float av[8] = {a0.x, a0.y, a0.z, a0.w, a1.x, a1.y, a1.z, a1.w};
            #pragma unroll
            for (int i = 0; i < 8; ++i) {
                unsigned long long ap;
                PACK_DUP(ap, av[i]);
                FMA2(acc[i][0], ap, bp0);
                FMA2(acc[i][1], ap, bp1);
                FMA2(acc[i][2], ap, bp2);
                FMA2(acc[i][3], ap, bp3);
            }
        }
        __syncthreads();
    }

    // Epilogue
    #pragma unroll
    for (int i = 0; i < 8; ++i) {
        int row = bm + ((i < 4) ? (ty4 + i) : (64 + ty4 + i - 4));
        float c0, c1, c2, c3, c4, c5, c6, c7;
        UNPK2(acc[i][0], c0, c1);
        UNPK2(acc[i][1], c2, c3);
        UNPK2(acc[i][2], c4, c5);
        UNPK2(acc[i][3], c6, c7);
        float4 lo = make_float4(c0, c1, c2, c3);
        float4 hi = make_float4(c4, c5, c6, c7);
        if (EPI) {
            float4 r0 = *(const float4*)(resid + (size_t)row * ldr + bn + tx4);
            float4 r1 = *(const float4*)(resid + (size_t)row * ldr + bn + 64 + tx4);
            lo.x += r0.x; lo.y += r0.y; lo.z += r0.z; lo.w += r0.w;
            hi.x += r1.x; hi.y += r1.y; hi.z += r1.z; hi.w += r1.w;
            lo.x = lo.x >= 0.f ? lo.x : SLOPE * lo.x;
            lo.y = lo.y >= 0.f ? lo.y : SLOPE * lo.y;
            lo.z = lo.z >= 0.f ? lo.z : SLOPE * lo.z;
            lo.w = lo.w >= 0.f ? lo.w : SLOPE * lo.w;
            hi.x = hi.x >= 0.f ? hi.x : SLOPE * hi.x;
            hi.y = hi.y >= 0.f ? hi.y : SLOPE * hi.y;
            hi.z = hi.z >= 0.f ? hi.z : SLOPE * hi.z;
            hi.w = hi.w >= 0.f ? hi.w : SLOPE * hi.w;
        }
        *(float4*)(C + (size_t)row * ldc + bn + tx4)      = lo;
        *(float4*)(C + (size_t)row * ldc + bn + 64 + tx4) = hi;
    }
}

// ---------------------------------------------------------------------------
// Row softmax (over full 8192 row) then multiply by adj, in-place on S.
// One block (256 threads) per row; row held in registers as 8x float4.
// ---------------------------------------------------------------------------
__global__ void softmax_mask_kernel(float* __restrict__ S,
                                    const float* __restrict__ adj)
{
    __shared__ float red[8];
    const int row = blockIdx.x;
    const int tid = threadIdx.x;
    float4* srow = (float4*)(S + (size_t)row * NNODES);
    const float4* arow = (const float4*)(adj + (size_t)row * NNODES);

    float4 v[8];
    float m = -3.4e38f;
    #pragma unroll
    for (int i = 0; i < 8; ++i) {
        v[i] = srow[tid + i * 256];
        m = fmaxf(m, fmaxf(fmaxf(v[i].x, v[i].y), fmaxf(v[i].z, v[i].w)));
    }
    #pragma unroll
    for (int o = 16; o > 0; o >>= 1)
        m = fmaxf(m, __shfl_xor_sync(0xffffffffu, m, o));
    if ((tid & 31) == 0) red[tid >> 5] = m;
    __syncthreads();
    m = red[0];
    #pragma unroll
    for (int i = 1; i < 8; ++i) m = fmaxf(m, red[i]);
    __syncthreads();

    float s = 0.f;
    #pragma unroll
    for (int i = 0; i < 8; ++i) {
        v[i].x = __expf(v[i].x - m);
        v[i].y = __expf(v[i].y - m);
        v[i].z = __expf(v[i].z - m);
        v[i].w = __expf(v[i].w - m);
        s += (v[i].x + v[i].y) + (v[i].z + v[i].w);
    }
    #pragma unroll
    for (int o = 16; o > 0; o >>= 1)
        s += __shfl_xor_sync(0xffffffffu, s, o);
    if ((tid & 31) == 0) red[tid >> 5] = s;
    __syncthreads();
    s = red[0];
    #pragma unroll
    for (int i = 1; i < 8; ++i) s += red[i];

    const float inv = 1.0f / s;
    #pragma unroll
    for (int i = 0; i < 8; ++i) {
        float4 a = arow[tid + i * 256];
        float4 o;
        o.x = v[i].x * inv * a.x;
        o.y = v[i].y * inv * a.y;
        o.z = v[i].z * inv * a.z;
        o.w = v[i].w * inv * a.w;
        srow[tid + i * 256] = o;
    }
}

// ---------------------------------------------------------------------------
extern "C" void kernel_launch(void* const* d_in, const int* in_sizes, int n_in,
                              void* d_out, int out_size)
{
    const float* x0   = (const float*)d_in[0];  // [8192, 512]
    const float* adj  = (const float*)d_in[1];  // [8192, 8192]
    const float* Wst  = (const float*)d_in[2];  // [2, 512, 1024]
    float* out = (float*)d_out;                 // [8192, 512]

    float *proj, *scores, *xbuf;
    cudaGetSymbolAddress((void**)&proj,   g_proj);
    cudaGetSymbolAddress((void**)&scores, g_scores);
    cudaGetSymbolAddress((void**)&xbuf,   g_xbuf);

    for (int l = 0; l < NLAYER; ++l) {
        const float* xin  = (l == 0) ? x0 : xbuf;
        float*       xout = (l == 0) ? xbuf : out;
        const float* W = Wst + (size_t)l * DIM * (2 * DIM);

        // proj[8192,1024] = xin[8192,512] @ W[512,1024]
        sgemm128<false, false><<<dim3((2 * DIM) / 128, NNODES / 128), 256>>>(
            xin, DIM, W, 2 * DIM, proj, 2 * DIM, nullptr, 0, DIM);

        // scores[8192,8192] = Wh @ Ws^T  (Wh = proj[:, :512], Ws = proj[:, 512:])
        sgemm128<true, false><<<dim3(NNODES / 128, NNODES / 128), 256>>>(
            proj, 2 * DIM, proj + DIM, 2 * DIM, scores, NNODES, nullptr, 0, DIM);

        // in-place: scores = softmax(scores, rows) * adj
        softmax_mask_kernel<<<NNODES, 256>>>(scores, adj);

        // xout = leaky(scores @ Wh + xin)
        sgemm128<false, true><<<dim3(DIM / 128, NNODES / 128), 256>>>(
            scores, NNODES, proj, 2 * DIM, xout, DIM, xin, DIM, NNODES);
    }
}

// round 4
// speedup vs baseline: 2.3292x; 2.3292x over previous
#include <cuda_runtime.h>
#include <cuda_bf16.h>
#include <cstdint>

#define NNODES 8192
#define DIM    512
#define NLAYER 2
#define SLOPE  0.01f

// ---------------------------------------------------------------------------
// Scratch (device globals; allocation-free per harness rules)
// ---------------------------------------------------------------------------
__device__ __align__(256) float g_scores[(size_t)NNODES * NNODES];   // 256 MB
__device__ __align__(256) float g_proj[NNODES * 2 * DIM];            // 32 MB
__device__ __align__(256) float g_xbuf[NNODES * DIM];                // 16 MB
__device__ __align__(256) __nv_bfloat16 g_projh[NNODES * 2 * DIM];
__device__ __align__(256) __nv_bfloat16 g_projl[NNODES * 2 * DIM];
__device__ __align__(256) __nv_bfloat16 g_sh[(size_t)NNODES * NNODES]; // 128 MB
__device__ __align__(256) __nv_bfloat16 g_sl[(size_t)NNODES * NNODES]; // 128 MB
__device__ __align__(256) __nv_bfloat16 g_whTh[DIM * NNODES];
__device__ __align__(256) __nv_bfloat16 g_whTl[DIM * NNODES];
__device__ __align__(256) __nv_bfloat16 g_xh[NNODES * DIM];
__device__ __align__(256) __nv_bfloat16 g_xl[NNODES * DIM];
__device__ __align__(256) __nv_bfloat16 g_wth[2 * DIM * DIM];
__device__ __align__(256) __nv_bfloat16 g_wtl[2 * DIM * DIM];

// ---------------------------------------------------------------------------
// Portable PTX helpers (all valid on base compute_103 target)
// ---------------------------------------------------------------------------
__device__ __forceinline__ uint32_t smem_u32(const void* p) {
    uint32_t a;
    asm("{ .reg .u64 t; cvta.to.shared.u64 t, %1; cvt.u32.u64 %0, t; }" : "=r"(a) : "l"(p));
    return a;
}
__device__ __forceinline__ uint32_t swz(uint32_t off) {
    return off ^ ((off >> 3) & 0x70);
}
__device__ __forceinline__ void cp16(uint32_t dst, const void* src) {
    asm volatile("cp.async.cg.shared.global [%0], [%1], 16;" :: "r"(dst), "l"(src));
}
__device__ __forceinline__ void ldm4(uint32_t addr, uint32_t r[4]) {
    asm volatile("ldmatrix.sync.aligned.m8n8.x4.shared.b16 {%0,%1,%2,%3}, [%4];"
                 : "=r"(r[0]), "=r"(r[1]), "=r"(r[2]), "=r"(r[3]) : "r"(addr));
}
__device__ __forceinline__ void mma_bf16(float* c, const uint32_t a[4],
                                         uint32_t b0, uint32_t b1) {
    asm volatile(
        "mma.sync.aligned.m16n8k16.row.col.f32.bf16.bf16.f32 "
        "{%0,%1,%2,%3}, {%4,%5,%6,%7}, {%8,%9}, {%0,%1,%2,%3};"
        : "+f"(c[0]), "+f"(c[1]), "+f"(c[2]), "+f"(c[3])
        : "r"(a[0]), "r"(a[1]), "r"(a[2]), "r"(a[3]), "r"(b0), "r"(b1));
}

// ---------------------------------------------------------------------------
// Split-bf16 HMMA GEMM: C[M,N](fp32) = (Ah+Al)[M,K] @ (Bh+Bl)[N,K]^T
// (drops Al*Bl). CTA tile 128x128, BK=32, cp.async double buffer.
// 8 warps, warp tile 64x32 (4 m-atoms x 4 n-atoms of m16n8k16).
// EPI: C = leaky_relu(acc + resid)
// ---------------------------------------------------------------------------
#define STAGE_BYTES 32768            // Ah 8K | Al 8K | Bh 8K | Bl 8K
#define GEMM_SMEM   (2 * STAGE_BYTES)

template <bool EPI>
__global__ __launch_bounds__(256, 2)
void gemm_mma(const __nv_bfloat16* __restrict__ Ah, const __nv_bfloat16* __restrict__ Al,
              int lda,
              const __nv_bfloat16* __restrict__ Bh, const __nv_bfloat16* __restrict__ Bl,
              int ldb,
              float* __restrict__ C, int ldc,
              const float* __restrict__ resid, int ldr, int K)
{
    extern __shared__ __align__(1024) char smch[];
    const uint32_t smb = smem_u32(smch);
    const int tid  = threadIdx.x;
    const int lane = tid & 31;
    const int wid  = tid >> 5;
    const int wm   = wid >> 2;      // 0..1  -> 64-row slab
    const int wn   = wid & 3;       // 0..3  -> 32-col slab
    const int bm = blockIdx.y * 128;
    const int bn = blockIdx.x * 128;

    const __nv_bfloat16* srcs[4] = {
        Ah + (size_t)bm * lda, Al + (size_t)bm * lda,
        Bh + (size_t)bn * ldb, Bl + (size_t)bn * ldb };

    // cp.async tile mapping: per array, 512 16B chunks; thread does 2.
    const int row0 = tid >> 2;             // rows tid/4 and 64 + tid/4
    const int seg  = tid & 3;              // 16B segment (8 bf16)
    const uint32_t soff0 = swz((row0 << 6) | (seg << 4));
    const uint32_t soff1 = swz(((row0 + 64) << 6) | (seg << 4));

    float acc[4][4][4];
    #pragma unroll
    for (int i = 0; i < 4; ++i)
        #pragma unroll
        for (int j = 0; j < 4; ++j)
            #pragma unroll
            for (int k = 0; k < 4; ++k) acc[i][j][k] = 0.f;

    // ldmatrix per-lane base byte offsets (unswizzled)
    const uint32_t a_base =
        (uint32_t)((wm * 64 + (lane & 15)) << 6) + ((lane >> 4) << 4);
    const uint32_t b_base =
        (uint32_t)((wn * 32 + (lane & 7) + ((lane >> 4) << 3)) << 6) + (((lane >> 3) & 1) << 4);

    const int T = K >> 5;   // BK=32 chunks

    // ---- stage loader ----
    auto load_stage = [&](int stg, int kt) {
        const uint32_t sb = smb + stg * STAGE_BYTES;
        #pragma unroll
        for (int h = 0; h < 4; ++h) {
            const int ld = (h < 2) ? lda : ldb;
            const __nv_bfloat16* base = srcs[h] + kt + seg * 8;
            cp16(sb + h * 8192 + soff0, base + (size_t)row0 * ld);
            cp16(sb + h * 8192 + soff1, base + (size_t)(row0 + 64) * ld);
        }
        asm volatile("cp.async.commit_group;");
    };

    load_stage(0, 0);

    for (int t = 0; t < T; ++t) {
        if (t + 1 < T) {
            load_stage((t + 1) & 1, (t + 1) << 5);
            asm volatile("cp.async.wait_group 1;");
        } else {
            asm volatile("cp.async.wait_group 0;");
        }
        __syncthreads();

        const uint32_t sb = smb + (t & 1) * STAGE_BYTES;
        #pragma unroll
        for (int kk = 0; kk < 2; ++kk) {          // two k16 steps
            const uint32_t kb = kk * 32;
            uint32_t af[4][4], bhf[2][4], blf[2][4];
            #pragma unroll
            for (int i = 0; i < 4; ++i)
                ldm4(sb + swz(a_base + i * 1024 + kb), af[i]);
            #pragma unroll
            for (int p = 0; p < 2; ++p)
                ldm4(sb + 16384 + swz(b_base + p * 1024 + kb), bhf[p]);
            #pragma unroll
            for (int p = 0; p < 2; ++p)
                ldm4(sb + 24576 + swz(b_base + p * 1024 + kb), blf[p]);

            // Ah*Bh
            #pragma unroll
            for (int i = 0; i < 4; ++i)
                #pragma unroll
                for (int p = 0; p < 2; ++p) {
                    mma_bf16(acc[i][2 * p + 0], af[i], bhf[p][0], bhf[p][1]);
                    mma_bf16(acc[i][2 * p + 1], af[i], bhf[p][2], bhf[p][3]);
                }
            // Ah*Bl
            #pragma unroll
            for (int i = 0; i < 4; ++i)
                #pragma unroll
                for (int p = 0; p < 2; ++p) {
                    mma_bf16(acc[i][2 * p + 0], af[i], blf[p][0], blf[p][1]);
                    mma_bf16(acc[i][2 * p + 1], af[i], blf[p][2], blf[p][3]);
                }
            // Al (overwrite af) * Bh
            #pragma unroll
            for (int i = 0; i < 4; ++i)
                ldm4(sb + 8192 + swz(a_base + i * 1024 + kb), af[i]);
            #pragma unroll
            for (int i = 0; i < 4; ++i)
                #pragma unroll
                for (int p = 0; p < 2; ++p) {
                    mma_bf16(acc[i][2 * p + 0], af[i], bhf[p][0], bhf[p][1]);
                    mma_bf16(acc[i][2 * p + 1], af[i], bhf[p][2], bhf[p][3]);
                }
        }
        __syncthreads();
    }

    // ---- epilogue ----
    #pragma unroll
    for (int i = 0; i < 4; ++i) {
        const int r0 = bm + wm * 64 + i * 16 + (lane >> 2);
        #pragma unroll
        for (int j = 0; j < 4; ++j) {
            const int col = bn + wn * 32 + j * 8 + (lane & 3) * 2;
            float v0 = acc[i][j][0], v1 = acc[i][j][1];
            float v2 = acc[i][j][2], v3 = acc[i][j][3];
            if (EPI) {
                const float* rp0 = resid + (size_t)r0 * ldr + col;
                const float* rp1 = resid + (size_t)(r0 + 8) * ldr + col;
                v0 += rp0[0]; v1 += rp0[1];
                v2 += rp1[0]; v3 += rp1[1];
                v0 = v0 >= 0.f ? v0 : SLOPE * v0;
                v1 = v1 >= 0.f ? v1 : SLOPE * v1;
                v2 = v2 >= 0.f ? v2 : SLOPE * v2;
                v3 = v3 >= 0.f ? v3 : SLOPE * v3;
            }
            *(float2*)(C + (size_t)r0 * ldc + col)       = make_float2(v0, v1);
            *(float2*)(C + (size_t)(r0 + 8) * ldc + col) = make_float2(v2, v3);
        }
    }
}

// ---------------------------------------------------------------------------
// fp32 -> (hi, lo) bf16, same layout (flat, vectorized by 4)
// ---------------------------------------------------------------------------
__global__ void split_rows_kernel(const float* __restrict__ in,
                                  __nv_bfloat16* __restrict__ h,
                                  __nv_bfloat16* __restrict__ l, size_t n4)
{
    size_t i = (size_t)blockIdx.x * blockDim.x + threadIdx.x;
    if (i >= n4) return;
    float4 v = ((const float4*)in)[i];
    __nv_bfloat16 hx = __float2bfloat16_rn(v.x);
    __nv_bfloat16 hy = __float2bfloat16_rn(v.y);
    __nv_bfloat16 hz = __float2bfloat16_rn(v.z);
    __nv_bfloat16 hw = __float2bfloat16_rn(v.w);
    __nv_bfloat162* h2 = (__nv_bfloat162*)h;
    __nv_bfloat162* l2 = (__nv_bfloat162*)l;
    h2[2 * i + 0] = __nv_bfloat162(hx, hy);
    h2[2 * i + 1] = __nv_bfloat162(hz, hw);
    l2[2 * i + 0] = __nv_bfloat162(__float2bfloat16_rn(v.x - __bfloat162float(hx)),
                                   __float2bfloat16_rn(v.y - __bfloat162float(hy)));
    l2[2 * i + 1] = __nv_bfloat162(__float2bfloat16_rn(v.z - __bfloat162float(hz)),
                                   __float2bfloat16_rn(v.w - __bfloat162float(hw)));
}

// ---------------------------------------------------------------------------
// fp32 [R x C] (ld=ldin) -> transposed (hi, lo) bf16 [C x R]
// ---------------------------------------------------------------------------
__global__ void splitT_kernel(const float* __restrict__ in, int ldin, int R,
                              __nv_bfloat16* __restrict__ h, __nv_bfloat16* __restrict__ l)
{
    __shared__ float t[32][33];
    const int c0 = blockIdx.x * 32, r0 = blockIdx.y * 32;
    #pragma unroll
    for (int j = 0; j < 4; ++j) {
        int r = r0 + threadIdx.y + j * 8;
        t[threadIdx.y + j * 8][threadIdx.x] = in[(size_t)r * ldin + c0 + threadIdx.x];
    }
    __syncthreads();
    #pragma unroll
    for (int j = 0; j < 4; ++j) {
        int c = c0 + threadIdx.y + j * 8;
        float v = t[threadIdx.x][threadIdx.y + j * 8];
        __nv_bfloat16 hv = __float2bfloat16_rn(v);
        h[(size_t)c * R + r0 + threadIdx.x] = hv;
        l[(size_t)c * R + r0 + threadIdx.x] =
            __float2bfloat16_rn(v - __bfloat162float(hv));
    }
}

// ---------------------------------------------------------------------------
// Row softmax * adj, emitting split bf16 (hi, lo). One block / row.
// ---------------------------------------------------------------------------
__global__ void softmax_mask_split_kernel(const float* __restrict__ S,
                                          const float* __restrict__ adj,
                                          __nv_bfloat16* __restrict__ sh,
                                          __nv_bfloat16* __restrict__ sl)
{
    __shared__ float red[8];
    const int row = blockIdx.x;
    const int tid = threadIdx.x;
    const float4* srow = (const float4*)(S + (size_t)row * NNODES);
    const float4* arow = (const float4*)(adj + (size_t)row * NNODES);

    float4 v[8];
    float m = -3.4e38f;
    #pragma unroll
    for (int i = 0; i < 8; ++i) {
        v[i] = srow[tid + i * 256];
        m = fmaxf(m, fmaxf(fmaxf(v[i].x, v[i].y), fmaxf(v[i].z, v[i].w)));
    }
    #pragma unroll
    for (int o = 16; o > 0; o >>= 1) m = fmaxf(m, __shfl_xor_sync(~0u, m, o));
    if ((tid & 31) == 0) red[tid >> 5] = m;
    __syncthreads();
    m = red[0];
    #pragma unroll
    for (int i = 1; i < 8; ++i) m = fmaxf(m, red[i]);
    __syncthreads();

    float s = 0.f;
    #pragma unroll
    for (int i = 0; i < 8; ++i) {
        v[i].x = __expf(v[i].x - m); v[i].y = __expf(v[i].y - m);
        v[i].z = __expf(v[i].z - m); v[i].w = __expf(v[i].w - m);
        s += (v[i].x + v[i].y) + (v[i].z + v[i].w);
    }
    #pragma unroll
    for (int o = 16; o > 0; o >>= 1) s += __shfl_xor_sync(~0u, s, o);
    if ((tid & 31) == 0) red[tid >> 5] = s;
    __syncthreads();
    s = red[0];
    #pragma unroll
    for (int i = 1; i < 8; ++i) s += red[i];

    const float inv = 1.0f / s;
    __nv_bfloat162* h2 = (__nv_bfloat162*)(sh + (size_t)row * NNODES);
    __nv_bfloat162* l2 = (__nv_bfloat162*)(sl + (size_t)row * NNODES);
    #pragma unroll
    for (int i = 0; i < 8; ++i) {
        float4 a = arow[tid + i * 256];
        float4 p;
        p.x = v[i].x * inv * a.x; p.y = v[i].y * inv * a.y;
        p.z = v[i].z * inv * a.z; p.w = v[i].w * inv * a.w;
        __nv_bfloat16 hx = __float2bfloat16_rn(p.x);
        __nv_bfloat16 hy = __float2bfloat16_rn(p.y);
        __nv_bfloat16 hz = __float2bfloat16_rn(p.z);
        __nv_bfloat16 hw = __float2bfloat16_rn(p.w);
        int idx = tid + i * 256;
        h2[2 * idx + 0] = __nv_bfloat162(hx, hy);
        h2[2 * idx + 1] = __nv_bfloat162(hz, hw);
        l2[2 * idx + 0] = __nv_bfloat162(__float2bfloat16_rn(p.x - __bfloat162float(hx)),
                                         __float2bfloat16_rn(p.y - __bfloat162float(hy)));
        l2[2 * idx + 1] = __nv_bfloat162(__float2bfloat16_rn(p.z - __bfloat162float(hz)),
                                         __float2bfloat16_rn(p.w - __bfloat162float(hw)));
    }
}

// ---------------------------------------------------------------------------
extern "C" void kernel_launch(void* const* d_in, const int* in_sizes, int n_in,
                              void* d_out, int out_size)
{
    const float* x0  = (const float*)d_in[0];  // [8192, 512]
    const float* adj = (const float*)d_in[1];  // [8192, 8192]
    const float* Wst = (const float*)d_in[2];  // [2, 512, 1024]
    float* out = (float*)d_out;

    cudaFuncSetAttribute(gemm_mma<false>, cudaFuncAttributeMaxDynamicSharedMemorySize, GEMM_SMEM);
    cudaFuncSetAttribute(gemm_mma<true>,  cudaFuncAttributeMaxDynamicSharedMemorySize, GEMM_SMEM);

    float *scores, *proj, *xbuf;
    __nv_bfloat16 *projh, *projl, *sh, *sl, *whTh, *whTl, *xh, *xl, *wth, *wtl;
    cudaGetSymbolAddress((void**)&scores, g_scores);
    cudaGetSymbolAddress((void**)&proj,   g_proj);
    cudaGetSymbolAddress((void**)&xbuf,   g_xbuf);
    cudaGetSymbolAddress((void**)&projh,  g_projh);
    cudaGetSymbolAddress((void**)&projl,  g_projl);
    cudaGetSymbolAddress((void**)&sh,     g_sh);
    cudaGetSymbolAddress((void**)&sl,     g_sl);
    cudaGetSymbolAddress((void**)&whTh,   g_whTh);
    cudaGetSymbolAddress((void**)&whTl,   g_whTl);
    cudaGetSymbolAddress((void**)&xh,     g_xh);
    cudaGetSymbolAddress((void**)&xl,     g_xl);
    cudaGetSymbolAddress((void**)&wth,    g_wth);
    cudaGetSymbolAddress((void**)&wtl,    g_wtl);

    for (int l = 0; l < NLAYER; ++l) {
        const float* xin  = l ? xbuf : x0;
        float*       xout = l ? out  : xbuf;
        const float* W = Wst + (size_t)l * DIM * (2 * DIM);

        // operand conversions
        {
            size_t n4 = (size_t)NNODES * DIM / 4;
            split_rows_kernel<<<(unsigned)((n4 + 255) / 256), 256>>>(xin, xh, xl, n4);
        }
        splitT_kernel<<<dim3(2 * DIM / 32, DIM / 32), dim3(32, 8)>>>(W, 2 * DIM, DIM, wth, wtl);

        // G1: proj[8192,1024] = x @ W
        gemm_mma<false><<<dim3(2 * DIM / 128, NNODES / 128), 256, GEMM_SMEM>>>(
            xh, xl, DIM, wth, wtl, DIM, proj, 2 * DIM, nullptr, 0, DIM);

        {
            size_t n4 = (size_t)NNODES * 2 * DIM / 4;
            split_rows_kernel<<<(unsigned)((n4 + 255) / 256), 256>>>(proj, projh, projl, n4);
        }
        // Wh^T split for the AV gemm (B operand [512, 8192])
        splitT_kernel<<<dim3(DIM / 32, NNODES / 32), dim3(32, 8)>>>(proj, 2 * DIM, NNODES,
                                                                    whTh, whTl);

        // G2: scores = Wh @ Ws^T
        gemm_mma<false><<<dim3(NNODES / 128, NNODES / 128), 256, GEMM_SMEM>>>(
            projh, projl, 2 * DIM, projh + DIM, projl + DIM, 2 * DIM,
            scores, NNODES, nullptr, 0, DIM);

        // softmax * adj -> split bf16
        softmax_mask_split_kernel<<<NNODES, 256>>>(scores, adj, sh, sl);

        // G3: xout = leaky(S @ Wh + xin)
        gemm_mma<true><<<dim3(DIM / 128, NNODES / 128), 256, GEMM_SMEM>>>(
            sh, sl, NNODES, whTh, whTl, NNODES, xout, DIM, xin, DIM, NNODES);
    }
}